// round 9
// baseline (speedup 1.0000x reference)
#include <cuda_runtime.h>
#include <cuda_fp16.h>
#include <stdint.h>

#define DEVI static __device__ __forceinline__

#define BATCH 512
#define DIM   512
#define NCLS  100000
#define NTILES 782            // ceil(100000/128)
#define NORM_CTAS 74          // producer CTAs (block ids 0..73 -> resident wave 1)
#define GRID_CTAS 296         // persistent CTAs (2 per SM x 148)
#define NGEMM (NTILES * 4)    // gemm work items

static constexpr float C_SCALE  = 64.0f;
static constexpr float C_ALPHA  = 1.2f;
static constexpr float C_COSM   =  0.87758256189037271612f;  // cos(0.5)
static constexpr float C_SINM   =  0.47942553860420300027f;  // sin(0.5)
static constexpr float C_THRESH = -0.87758256189037271612f;  // cos(pi-0.5)
static constexpr float C_MM     =  0.23971276930210150013f;  // sin(0.5)*0.5

// ---- device-global scratch (no allocation allowed) ----
__device__ __align__(1024) __half g_Ah[BATCH * DIM];
__device__ __align__(1024) __half g_Bh[(size_t)NCLS * DIM];
__device__ float g_target[BATCH];
__device__ int   g_label[BATCH];
__device__ volatile int g_flag[NTILES];
__device__ int   g_gemm_ctr;

// ---------------- PTX helpers ----------------
DEVI uint32_t smem_u32(const void* p) {
    uint32_t a;
    asm("{ .reg .u64 t; cvta.to.shared.u64 t, %1; cvt.u32.u64 %0, t; }" : "=r"(a) : "l"(p));
    return a;
}
DEVI void cp_async16(uint32_t dst, const void* src) {
    asm volatile("cp.async.cg.shared.global [%0], [%1], 16;" :: "r"(dst), "l"(src) : "memory");
}
DEVI void cp_commit() { asm volatile("cp.async.commit_group;" ::: "memory"); }
template <int N> DEVI void cp_wait() {
    asm volatile("cp.async.wait_group %0;" :: "n"(N) : "memory");
}
DEVI void ldsm_x4(uint32_t* r, uint32_t addr) {
    asm volatile("ldmatrix.sync.aligned.m8n8.x4.shared.b16 {%0,%1,%2,%3}, [%4];"
                 : "=r"(r[0]), "=r"(r[1]), "=r"(r[2]), "=r"(r[3]) : "r"(addr));
}
DEVI void mma16816(float* d, const uint32_t* a, uint32_t b0, uint32_t b1) {
    asm volatile(
        "mma.sync.aligned.m16n8k16.row.col.f32.f16.f16.f32 "
        "{%0,%1,%2,%3}, {%4,%5,%6,%7}, {%8,%9}, {%0,%1,%2,%3};"
        : "+f"(d[0]), "+f"(d[1]), "+f"(d[2]), "+f"(d[3])
        : "r"(a[0]), "r"(a[1]), "r"(a[2]), "r"(a[3]), "r"(b0), "r"(b1));
}
DEVI void norm_row_store(const float4* sp, __half* dst, int lane) {
    float4 v[4];
    float ss = 0.f;
#pragma unroll
    for (int i = 0; i < 4; i++) {
        v[i] = sp[lane + 32 * i];
        ss += v[i].x * v[i].x + v[i].y * v[i].y + v[i].z * v[i].z + v[i].w * v[i].w;
    }
#pragma unroll
    for (int o = 16; o > 0; o >>= 1) ss += __shfl_xor_sync(0xFFFFFFFFu, ss, o);
    float r = rsqrtf(ss);
    r = r * (1.5f - 0.5f * ss * r * r);
    uint2* dp = (uint2*)dst;
#pragma unroll
    for (int i = 0; i < 4; i++) {
        __half h0 = __float2half_rn(v[i].x * r);
        __half h1 = __float2half_rn(v[i].y * r);
        __half h2 = __float2half_rn(v[i].z * r);
        __half h3 = __float2half_rn(v[i].w * r);
        __half2 p01 = __halves2half2(h0, h1);
        __half2 p23 = __halves2half2(h2, h3);
        uint2 u;
        u.x = *(uint32_t*)&p01;
        u.y = *(uint32_t*)&p23;
        dp[lane + 32 * i] = u;
    }
}

// ---------------- kernel 1: prep (state reset + label fix + norm_x + exact target) ----------------
__global__ void prep_kernel(const float* __restrict__ x,
                            const int* __restrict__ lraw,
                            const float* __restrict__ w)
{
    __shared__ int s_or;
    const int tid  = threadIdx.x;
    const int wid  = tid >> 5;
    const int lane = tid & 31;
    const int b    = blockIdx.x * 8 + wid;

    // reset flags + work counter (same stream; ordered before fused kernel)
    {
        int i = blockIdx.x * 256 + tid;
        if (i < NTILES) g_flag[i] = 0;
        if (i == 0) g_gemm_ctr = 0;
    }

    if (tid == 0) s_or = 0;
    __syncthreads();
    if (tid < 256) {
        if (lraw[2 * tid + 1] != 0) atomicOr(&s_or, 1);
    }
    __syncthreads();
    const int lb = s_or ? lraw[b] : lraw[2 * b];
    if (lane == 0) g_label[b] = lb;

    const float4* xp = (const float4*)(x + (size_t)b * DIM);
    const float4* wp = (const float4*)(w + (size_t)lb * DIM);
    float4 v[4];
    float xx = 0.f, ww = 0.f, xw = 0.f;
#pragma unroll
    for (int i = 0; i < 4; i++) {
        v[i] = xp[lane + 32 * i];
        float4 c = wp[lane + 32 * i];
        xx += v[i].x * v[i].x + v[i].y * v[i].y + v[i].z * v[i].z + v[i].w * v[i].w;
        ww += c.x * c.x + c.y * c.y + c.z * c.z + c.w * c.w;
        xw += v[i].x * c.x + v[i].y * c.y + v[i].z * c.z + v[i].w * c.w;
    }
#pragma unroll
    for (int o = 16; o > 0; o >>= 1) {
        xx += __shfl_xor_sync(0xFFFFFFFFu, xx, o);
        ww += __shfl_xor_sync(0xFFFFFFFFu, ww, o);
        xw += __shfl_xor_sync(0xFFFFFFFFu, xw, o);
    }

    float rx = rsqrtf(xx);
    rx = rx * (1.5f - 0.5f * xx * rx * rx);
    uint2* dp = (uint2*)(g_Ah + (size_t)b * DIM);
#pragma unroll
    for (int i = 0; i < 4; i++) {
        __half h0 = __float2half_rn(v[i].x * rx);
        __half h1 = __float2half_rn(v[i].y * rx);
        __half h2 = __float2half_rn(v[i].z * rx);
        __half h3 = __float2half_rn(v[i].w * rx);
        __half2 p01 = __halves2half2(h0, h1);
        __half2 p23 = __halves2half2(h2, h3);
        uint2 u;
        u.x = *(uint32_t*)&p01;
        u.y = *(uint32_t*)&p23;
        dp[lane + 32 * i] = u;
    }

    if (lane == 0) {
        float p = xx * ww;
        float r = rsqrtf(p);
        r = r * (1.5f - 0.5f * p * r * r);
        float c = xw * r;
        float tgt = (c > C_THRESH)
                        ? (c * C_COSM - C_SINM * sqrtf(fmaxf(1.f - c * c, 0.f)))
                        : (c - C_MM);
        g_target[b] = tgt;
    }
}

// ---------------- kernel 2: persistent fused norm producers + GEMM consumers ----------------
// 296 CTAs. CTAs 0..73 first normalize w tiles round-robin (setting g_flag),
// then convert to GEMM consumers. All consumers pull tiles from g_gemm_ctr.
// GEMM tile g: by = g>>2 (n tile), bx = g&3 (m tile) -> adjacent g share B in L2.
__global__ __launch_bounds__(256)
void fused_kernel(const float* __restrict__ w, float* __restrict__ out)
{
    extern __shared__ char smem[];
    __shared__ int s_tile;
    const uint32_t sbase = smem_u32(smem);
    const int tid  = threadIdx.x;
    const int wid  = tid >> 5;
    const int lane = tid & 31;

    // ---- producer phase (CTAs 0..73) ----
    if (blockIdx.x < NORM_CTAS) {
        for (int t = blockIdx.x; t < NTILES; t += NORM_CTAS) {
            const int row0 = t * 128 + wid * 16;   // each warp: 16 rows
#pragma unroll 2
            for (int rp = 0; rp < 16; rp++) {
                const int r = row0 + rp;
                if (r < NCLS)
                    norm_row_store((const float4*)(w + (size_t)r * DIM),
                                   g_Bh + (size_t)r * DIM, lane);
            }
            __syncthreads();
            __threadfence();
            if (tid == 0) g_flag[t] = 1;
        }
    }

    const char* Ag = (const char*)g_Ah;
    const char* Bg = (const char*)g_Bh;
    const int wm  = (wid & 1) * 64;
    const int wn  = (wid >> 1) * 32;

    // ---- consumer loop: steal GEMM tiles ----
    for (;;) {
        if (tid == 0) s_tile = atomicAdd(&g_gemm_ctr, 1);
        __syncthreads();
        const int g = s_tile;
        if (g >= NGEMM) break;
        const int by = g >> 2;
        const int m0 = (g & 3) * 128;
        const int n0 = by * 128;

        // wait for this n-tile's normalized B rows
        if (tid == 0) {
            while (g_flag[by] == 0) __nanosleep(128);
        }
        __syncthreads();
        __threadfence();

        float acc[4][4][4];
#pragma unroll
        for (int mt = 0; mt < 4; mt++)
#pragma unroll
            for (int nt = 0; nt < 4; nt++)
#pragma unroll
                for (int i = 0; i < 4; i++) acc[mt][nt][i] = 0.f;

        auto load_chunk = [&](int s, int kc) {
            const uint32_t sA = sbase + s * 32768;
            const uint32_t sB = sA + 16384;
#pragma unroll
            for (int it = 0; it < 4; it++) {
                int u = tid + 256 * it;          // 1024 granules of 16B
                int row = u >> 3;
                int c   = u & 7;
                uint32_t soff = (uint32_t)(row * 128 + ((c ^ (row & 7)) << 4));
                cp_async16(sA + soff, Ag + ((size_t)(m0 + row) * 512 + kc * 64 + c * 8) * 2);
                int gr = n0 + row; if (gr >= NCLS) gr = NCLS - 1;
                cp_async16(sB + soff, Bg + ((size_t)gr * 512 + kc * 64 + c * 8) * 2);
            }
            cp_commit();
        };

        load_chunk(0, 0);
        load_chunk(1, 1);

        int stage = 0;
        for (int kc = 0; kc < 8; kc++) {
            if (kc < 7) cp_wait<1>(); else cp_wait<0>();
            __syncthreads();

            const uint32_t sA = sbase + stage * 32768;
            const uint32_t sB = sA + 16384;
#pragma unroll
            for (int ks = 0; ks < 4; ks++) {
                uint32_t a[4][4];
#pragma unroll
                for (int mt = 0; mt < 4; mt++) {
                    int row = wm + mt * 16 + (lane & 15);
                    int gr  = ks * 2 + (lane >> 4);
                    ldsm_x4(a[mt], sA + row * 128 + (((uint32_t)gr ^ (row & 7)) << 4));
                }
                uint32_t b[2][4];
#pragma unroll
                for (int p = 0; p < 2; p++) {
                    int nr = wn + p * 16 + (lane & 7) + ((lane >> 4) << 3);
                    int gr = ks * 2 + ((lane >> 3) & 1);
                    ldsm_x4(b[p], sB + nr * 128 + (((uint32_t)gr ^ (nr & 7)) << 4));
                }
#pragma unroll
                for (int mt = 0; mt < 4; mt++)
#pragma unroll
                    for (int nt = 0; nt < 4; nt++)
                        mma16816(acc[mt][nt], a[mt], b[nt >> 1][(nt & 1) * 2],
                                 b[nt >> 1][(nt & 1) * 2 + 1]);
                // issue the next-chunk loads after the first ks block, away
                // from the post-barrier ldmatrix burst
                if (ks == 0 && kc + 2 < 8) {
                    int ns = stage + 2; if (ns >= 3) ns -= 3;
                    load_chunk(ns, kc + 2);
                }
            }
            stage++; if (stage >= 3) stage = 0;
        }

        // ---- fused ArcNegFace epilogue ----
#pragma unroll
        for (int mt = 0; mt < 4; mt++) {
            const int r0 = m0 + wm + mt * 16 + (lane >> 2);
            const int r1 = r0 + 8;
            const float tg0 = g_target[r0], tg1 = g_target[r1];
            const int lb0 = g_label[r0],  lb1 = g_label[r1];
            float* o0 = out + (size_t)r0 * NCLS;
            float* o1 = out + (size_t)r1 * NCLS;
#pragma unroll
            for (int nt = 0; nt < 4; nt++) {
                const int c0 = n0 + wn + nt * 8 + 2 * (lane & 3);
                if (c0 >= NCLS) continue;   // NCLS even -> pair all-or-nothing
                float v[4];
#pragma unroll
                for (int i = 0; i < 4; i++) {
                    const float cs  = acc[mt][nt][i];
                    const float tg  = (i < 2) ? tg0 : tg1;
                    const int   lb  = (i < 2) ? lb0 : lb1;
                    const float dd  = cs - tg;
                    const float ts  = C_ALPHA * __expf(-0.5f * dd * dd);
                    float r = C_SCALE * (ts * cs + ts - 1.0f);
                    if (c0 + (i & 1) == lb) v[i] = C_SCALE * tg; else v[i] = r;
                }
                *(float2*)(o0 + c0) = make_float2(v[0], v[1]);
                *(float2*)(o1 + c0) = make_float2(v[2], v[3]);
            }
        }
        __syncthreads();   // protect s_tile before next steal
    }
}

// ---------------- launcher (2 launches, single stream) ----------------
extern "C" void kernel_launch(void* const* d_in, const int* in_sizes, int n_in,
                              void* d_out, int out_size)
{
    const float* x     = (const float*)d_in[0];
    const int*   lraw  = (const int*)d_in[1];
    const float* w     = (const float*)d_in[2];
    float*       out   = (float*)d_out;

    cudaFuncSetAttribute(fused_kernel, cudaFuncAttributeMaxDynamicSharedMemorySize, 98304);

    prep_kernel<<<BATCH / 8, 256>>>(x, lraw, w);
    fused_kernel<<<GRID_CTAS, 256, 98304>>>(w, out);
}

// round 10
// speedup vs baseline: 1.2770x; 1.2770x over previous
#include <cuda_runtime.h>
#include <cuda_fp16.h>
#include <stdint.h>

#define DEVI static __device__ __forceinline__

#define BATCH 512
#define DIM   512
#define NCLS  100000
#define NTILES 782            // ceil(100000/128)
#define NORMW_CTAS 12500      // NCLS/8 rows per CTA (8 warps x 1 row)

static constexpr float C_SCALE  = 64.0f;
static constexpr float C_ALPHA  = 1.2f;
static constexpr float C_COSM   =  0.87758256189037271612f;  // cos(0.5)
static constexpr float C_SINM   =  0.47942553860420300027f;  // sin(0.5)
static constexpr float C_THRESH = -0.87758256189037271612f;  // cos(pi-0.5)
static constexpr float C_MM     =  0.23971276930210150013f;  // sin(0.5)*0.5

// ---- device-global scratch (no allocation allowed) ----
__device__ __align__(1024) __half g_Ah[BATCH * DIM];
__device__ __align__(1024) __half g_Bh[(size_t)NCLS * DIM];
__device__ float g_target[BATCH];
__device__ int   g_label[BATCH];

// ---------------- PTX helpers ----------------
DEVI uint32_t smem_u32(const void* p) {
    uint32_t a;
    asm("{ .reg .u64 t; cvta.to.shared.u64 t, %1; cvt.u32.u64 %0, t; }" : "=r"(a) : "l"(p));
    return a;
}
DEVI void cp_async16(uint32_t dst, const void* src) {
    asm volatile("cp.async.cg.shared.global [%0], [%1], 16;" :: "r"(dst), "l"(src) : "memory");
}
DEVI void cp_commit() { asm volatile("cp.async.commit_group;" ::: "memory"); }
template <int N> DEVI void cp_wait() {
    asm volatile("cp.async.wait_group %0;" :: "n"(N) : "memory");
}
DEVI void ldsm_x4(uint32_t* r, uint32_t addr) {
    asm volatile("ldmatrix.sync.aligned.m8n8.x4.shared.b16 {%0,%1,%2,%3}, [%4];"
                 : "=r"(r[0]), "=r"(r[1]), "=r"(r[2]), "=r"(r[3]) : "r"(addr));
}
DEVI void mma16816(float* d, const uint32_t* a, uint32_t b0, uint32_t b1) {
    asm volatile(
        "mma.sync.aligned.m16n8k16.row.col.f32.f16.f16.f32 "
        "{%0,%1,%2,%3}, {%4,%5,%6,%7}, {%8,%9}, {%0,%1,%2,%3};"
        : "+f"(d[0]), "+f"(d[1]), "+f"(d[2]), "+f"(d[3])
        : "r"(a[0]), "r"(a[1]), "r"(a[2]), "r"(a[3]), "r"(b0), "r"(b1));
}
DEVI void norm_row_store(const float4* sp, __half* dst, int lane) {
    float4 v[4];
    float ss = 0.f;
#pragma unroll
    for (int i = 0; i < 4; i++) {
        v[i] = sp[lane + 32 * i];
        ss += v[i].x * v[i].x + v[i].y * v[i].y + v[i].z * v[i].z + v[i].w * v[i].w;
    }
#pragma unroll
    for (int o = 16; o > 0; o >>= 1) ss += __shfl_xor_sync(0xFFFFFFFFu, ss, o);
    float r = rsqrtf(ss);
    r = r * (1.5f - 0.5f * ss * r * r);   // NR refine -> ~fp32 exact
    uint2* dp = (uint2*)dst;
#pragma unroll
    for (int i = 0; i < 4; i++) {
        __half h0 = __float2half_rn(v[i].x * r);
        __half h1 = __float2half_rn(v[i].y * r);
        __half h2 = __float2half_rn(v[i].z * r);
        __half h3 = __float2half_rn(v[i].w * r);
        __half2 p01 = __halves2half2(h0, h1);
        __half2 p23 = __halves2half2(h2, h3);
        uint2 u;
        u.x = *(uint32_t*)&p01;
        u.y = *(uint32_t*)&p23;
        dp[lane + 32 * i] = u;
    }
}

// ---------------- kernel 1: norm_w (blocks 0..12499) + prep (blocks 12500..12563) ----------------
__global__ void prep_norm_kernel(const float* __restrict__ w,
                                 const float* __restrict__ x,
                                 const int* __restrict__ lraw)
{
    const int tid  = threadIdx.x;
    const int wid  = tid >> 5;
    const int lane = tid & 31;

    if (blockIdx.x < NORMW_CTAS) {
        // ---- normalize one w row per warp ----
        const int row = blockIdx.x * 8 + wid;
        if (row < NCLS)
            norm_row_store((const float4*)(w + (size_t)row * DIM),
                           g_Bh + (size_t)row * DIM, lane);
        return;
    }

    // ---- prep path: label fix + norm_x + exact fp32 target ----
    __shared__ int s_or;
    const int b = (blockIdx.x - NORMW_CTAS) * 8 + wid;

    if (tid == 0) s_or = 0;
    __syncthreads();
    if (tid < 256) {
        if (lraw[2 * tid + 1] != 0) atomicOr(&s_or, 1);
    }
    __syncthreads();
    const int lb = s_or ? lraw[b] : lraw[2 * b];   // int32 vs int64 low word
    if (lane == 0) g_label[b] = lb;

    const float4* xp = (const float4*)(x + (size_t)b * DIM);
    const float4* wp = (const float4*)(w + (size_t)lb * DIM);
    float4 v[4];
    float xx = 0.f, ww = 0.f, xw = 0.f;
#pragma unroll
    for (int i = 0; i < 4; i++) {
        v[i] = xp[lane + 32 * i];
        float4 c = wp[lane + 32 * i];
        xx += v[i].x * v[i].x + v[i].y * v[i].y + v[i].z * v[i].z + v[i].w * v[i].w;
        ww += c.x * c.x + c.y * c.y + c.z * c.z + c.w * c.w;
        xw += v[i].x * c.x + v[i].y * c.y + v[i].z * c.z + v[i].w * c.w;
    }
#pragma unroll
    for (int o = 16; o > 0; o >>= 1) {
        xx += __shfl_xor_sync(0xFFFFFFFFu, xx, o);
        ww += __shfl_xor_sync(0xFFFFFFFFu, ww, o);
        xw += __shfl_xor_sync(0xFFFFFFFFu, xw, o);
    }

    float rx = rsqrtf(xx);
    rx = rx * (1.5f - 0.5f * xx * rx * rx);
    uint2* dp = (uint2*)(g_Ah + (size_t)b * DIM);
#pragma unroll
    for (int i = 0; i < 4; i++) {
        __half h0 = __float2half_rn(v[i].x * rx);
        __half h1 = __float2half_rn(v[i].y * rx);
        __half h2 = __float2half_rn(v[i].z * rx);
        __half h3 = __float2half_rn(v[i].w * rx);
        __half2 p01 = __halves2half2(h0, h1);
        __half2 p23 = __halves2half2(h2, h3);
        uint2 u;
        u.x = *(uint32_t*)&p01;
        u.y = *(uint32_t*)&p23;
        dp[lane + 32 * i] = u;
    }

    if (lane == 0) {
        float p = xx * ww;
        float r = rsqrtf(p);
        r = r * (1.5f - 0.5f * p * r * r);
        float c = xw * r;
        float tgt = (c > C_THRESH)
                        ? (c * C_COSM - C_SINM * sqrtf(fmaxf(1.f - c * c, 0.f)))
                        : (c - C_MM);
        g_target[b] = tgt;
    }
}

// ---------------- kernel 2: mma.sync GEMM + fused ArcNegFace epilogue ----------------
// CTA tile 128M x 128N, K=512 in 8 chunks of 64, 3-stage cp.async pipeline,
// kc loop FULLY UNROLLED so stage bases & swizzled addresses fold to immediates.
// 8 warps: warp tile 64M x 32N. SMEM per stage: A 16KB + B 16KB; 3 stages = 96KB.
__global__ __launch_bounds__(256)
void gemm_kernel(float* __restrict__ out)
{
    extern __shared__ char smem[];
    const uint32_t sbase = smem_u32(smem);
    const int tid  = threadIdx.x;
    const int wid  = tid >> 5;
    const int lane = tid & 31;
    const int m0   = blockIdx.x * 128;   // 4 m-tiles fastest -> share B tile in L2
    const int n0   = blockIdx.y * 128;
    const int wm   = (wid & 1) * 64;
    const int wn   = (wid >> 1) * 32;

    const char* Ag = (const char*)g_Ah;
    const char* Bg = (const char*)g_Bh;

    float acc[4][4][4];
#pragma unroll
    for (int mt = 0; mt < 4; mt++)
#pragma unroll
        for (int nt = 0; nt < 4; nt++)
#pragma unroll
            for (int i = 0; i < 4; i++) acc[mt][nt][i] = 0.f;

    // per-thread constant pieces of the load addresses
    const int l_row = tid >> 3;           // 0..31 (row granule base)
    const int l_c   = tid & 7;            // 16B segment
    const uint32_t l_soff0 = (uint32_t)(l_row * 128 + ((l_c ^ (l_row & 7)) << 4));
    const size_t l_ga = (size_t)(m0 + l_row) * 512 + l_c * 8;

    auto load_chunk = [&](uint32_t sA, int kc) {
        const uint32_t sB = sA + 16384;
#pragma unroll
        for (int it = 0; it < 4; it++) {
            int row = l_row + 32 * it;
            uint32_t soff = l_soff0 + (uint32_t)(32 * it * 128);
            cp_async16(sA + soff, Ag + (l_ga + (size_t)32 * it * 512 + kc * 64) * 2);
            int gr = n0 + row; if (gr >= NCLS) gr = NCLS - 1;
            cp_async16(sB + soff, Bg + (((size_t)gr * 512 + l_c * 8) + kc * 64) * 2);
        }
        cp_commit();
    };

    // per-warp constant ldsm address bases (swizzle XOR folded per-ks below)
    load_chunk(sbase, 0);
    load_chunk(sbase + 32768, 1);

#pragma unroll
    for (int kc = 0; kc < 8; kc++) {
        const int stage = kc % 3;                       // compile-time
        const uint32_t sA = sbase + stage * 32768;      // immediate
        const uint32_t sB = sA + 16384;
        if (kc < 7) cp_wait<1>(); else cp_wait<0>();
        __syncthreads();
        if (kc + 2 < 8)
            load_chunk(sbase + ((kc + 2) % 3) * 32768, kc + 2);

#pragma unroll
        for (int ks = 0; ks < 4; ks++) {
            uint32_t a[4][4];
#pragma unroll
            for (int mt = 0; mt < 4; mt++) {
                int row = wm + mt * 16 + (lane & 15);
                int gr  = ks * 2 + (lane >> 4);
                ldsm_x4(a[mt], sA + row * 128 + (((uint32_t)gr ^ (row & 7)) << 4));
            }
            uint32_t b[2][4];
#pragma unroll
            for (int p = 0; p < 2; p++) {
                int nr = wn + p * 16 + (lane & 7) + ((lane >> 4) << 3);
                int gr = ks * 2 + ((lane >> 3) & 1);
                ldsm_x4(b[p], sB + nr * 128 + (((uint32_t)gr ^ (nr & 7)) << 4));
            }
#pragma unroll
            for (int mt = 0; mt < 4; mt++)
#pragma unroll
                for (int nt = 0; nt < 4; nt++)
                    mma16816(acc[mt][nt], a[mt], b[nt >> 1][(nt & 1) * 2],
                             b[nt >> 1][(nt & 1) * 2 + 1]);
        }
    }

    // ---- fused ArcNegFace epilogue ----
#pragma unroll
    for (int mt = 0; mt < 4; mt++) {
        const int r0 = m0 + wm + mt * 16 + (lane >> 2);
        const int r1 = r0 + 8;
        const float tg0 = g_target[r0], tg1 = g_target[r1];
        const int lb0 = g_label[r0],  lb1 = g_label[r1];
        float* o0 = out + (size_t)r0 * NCLS;
        float* o1 = out + (size_t)r1 * NCLS;
#pragma unroll
        for (int nt = 0; nt < 4; nt++) {
            const int c0 = n0 + wn + nt * 8 + 2 * (lane & 3);
            if (c0 >= NCLS) continue;   // NCLS even, c0 even -> pair all-or-nothing
            float v[4];
#pragma unroll
            for (int i = 0; i < 4; i++) {
                const float cs  = acc[mt][nt][i];
                const float tg  = (i < 2) ? tg0 : tg1;
                const int   lb  = (i < 2) ? lb0 : lb1;
                const float dd  = cs - tg;
                const float ts  = C_ALPHA * __expf(-0.5f * dd * dd);
                float r = C_SCALE * (ts * cs + ts - 1.0f);
                if (c0 + (i & 1) == lb) r = C_SCALE * tg;
                v[i] = r;
            }
            *(float2*)(o0 + c0) = make_float2(v[0], v[1]);
            *(float2*)(o1 + c0) = make_float2(v[2], v[3]);
        }
    }
}

// ---------------- launcher (2 launches, single stream) ----------------
extern "C" void kernel_launch(void* const* d_in, const int* in_sizes, int n_in,
                              void* d_out, int out_size)
{
    const float* x     = (const float*)d_in[0];
    const int*   lraw  = (const int*)d_in[1];
    const float* w     = (const float*)d_in[2];
    float*       out   = (float*)d_out;

    cudaFuncSetAttribute(gemm_kernel, cudaFuncAttributeMaxDynamicSharedMemorySize, 98304);

    prep_norm_kernel<<<NORMW_CTAS + BATCH / 8, 256>>>(w, x, lraw);

    dim3 grid(4, NTILES);
    gemm_kernel<<<grid, 256, 98304>>>(out);
}